// round 1
// baseline (speedup 1.0000x reference)
#include <cuda_runtime.h>

#define HOP 160
#define NFFT 512
#define NMEL 64
#define NFREQ 257          // NFFT/2+1
#define PREEMPH 0.97f
#define LOG_GUARD 5.9604644775390625e-8f   // 2^-24

#define MAXB 32
#define MAXT 1601

// ---- device scratch (no allocations allowed) ----
__device__ float2 g_S[NFREQ];                    // exp(-i*pi*f/256), f=0..256
__device__ int    g_lo[NMEL], g_hi[NMEL];        // sparse support of mel filters
__device__ float  g_mean[MAXB * NMEL];
__device__ float  g_rstd[MAXB * NMEL];
__device__ float  g_logmel[(size_t)MAXB * MAXT * NMEL];   // [b, t, m] layout

// ---------------------------------------------------------------------------
// init: twiddle table + mel filter support ranges
// ---------------------------------------------------------------------------
__global__ void init_kernel(const float* __restrict__ fb) {
    int tid = threadIdx.x;
    if (tid < NFREQ) {
        float s, c;
        sincospif((float)tid / 256.0f, &s, &c);
        g_S[tid] = make_float2(c, -s);           // exp(-i*theta)
    }
    if (tid >= 288 && tid < 288 + NMEL) {
        int m = tid - 288;
        int lo = NFREQ, hi = -1;
        const float* row = fb + m * NFREQ;
        for (int f = 0; f < NFREQ; f++) {
            if (row[f] != 0.0f) { if (f < lo) lo = f; hi = f; }
        }
        g_lo[m] = lo;
        g_hi[m] = hi;
    }
}

// ---------------------------------------------------------------------------
// frame kernel: one block per (t, b) frame.
// preemph + reflect pad + window -> 256pt complex Stockham FFT (real packing)
// -> power spectrum -> sparse mel -> log -> scratch [b,t,m]
// ---------------------------------------------------------------------------
__global__ __launch_bounds__(128) void frame_kernel(
    const float* __restrict__ x, const float* __restrict__ win,
    const float* __restrict__ fb, int L, int T)
{
    __shared__ float2 bufA[256];
    __shared__ float2 bufB[256];
    __shared__ float2 Ssh[NFREQ];
    __shared__ float  pow_s[NFREQ];

    const int tid = threadIdx.x;
    const int t = blockIdx.x;
    const int b = blockIdx.y;
    const float* xb = x + (size_t)b * L;

    // copy twiddle table to shared
    for (int i = tid; i < NFREQ; i += 128) Ssh[i] = g_S[i];

    // pack: z[k] = y(2k) + i*y(2k+1); y = window * preemph(reflect-padded x)
    const int base = t * HOP - (NFFT / 2);
    #pragma unroll
    for (int kk = 0; kk < 2; kk++) {
        int k = tid + kk * 128;
        float vr = 0.0f, vi = 0.0f;
        {
            int n = 2 * k;
            float wn = win[n];
            if (wn != 0.0f) {
                int q = base + n;
                if (q < 0) q = -q;
                if (q >= L) q = 2 * (L - 1) - q;
                float y = (q == 0) ? xb[0] : (xb[q] - PREEMPH * xb[q - 1]);
                vr = wn * y;
            }
        }
        {
            int n = 2 * k + 1;
            float wn = win[n];
            if (wn != 0.0f) {
                int q = base + n;
                if (q < 0) q = -q;
                if (q >= L) q = 2 * (L - 1) - q;
                float y = (q == 0) ? xb[0] : (xb[q] - PREEMPH * xb[q - 1]);
                vi = wn * y;
            }
        }
        bufA[k] = make_float2(vr, vi);
    }
    __syncthreads();

    // 256-point Stockham DIF radix-2, 8 stages, 1 butterfly/thread/stage.
    // Level st: stride s = 2^st, p = tid >> st, twiddle = exp(-2*pi*i*p*s/256)
    float2* src = bufA;
    float2* dst = bufB;
    #pragma unroll
    for (int st = 0; st < 8; st++) {
        int p = tid >> st;
        float2 w = Ssh[p << (st + 1)];           // exp(-i*pi*(2*p*s)/256)
        float2 a = src[tid];
        float2 c = src[tid + 128];
        float sr = a.x + c.x, si = a.y + c.y;
        float dr = a.x - c.x, di = a.y - c.y;
        int o = tid + (p << st);
        dst[o] = make_float2(sr, si);
        dst[o + (1 << st)] = make_float2(dr * w.x - di * w.y,
                                         dr * w.y + di * w.x);
        __syncthreads();
        float2* tmp = src; src = dst; dst = tmp;
    }
    // result Z (natural order) is in src (== bufA after 8 swaps)

    // real-FFT split: Y[f] = E[f] + S[f]*O[f]; power spectrum
    #pragma unroll
    for (int kk = 0; kk < 2; kk++) {
        int f = tid + kk * 128;                  // 0..255
        int g = (256 - f) & 255;
        float2 zf = src[f];
        float2 zg = src[g];
        float er = 0.5f * (zf.x + zg.x);
        float ei = 0.5f * (zf.y - zg.y);
        float orr = 0.5f * (zf.y + zg.y);
        float oi  = -0.5f * (zf.x - zg.x);
        float2 w = Ssh[f];
        float yr = er + w.x * orr - w.y * oi;
        float yi = ei + w.x * oi + w.y * orr;
        pow_s[f] = yr * yr + yi * yi;
    }
    if (tid == 0) {
        float2 z0 = src[0];
        float d = z0.x - z0.y;                   // Y[256] = Re(Z0) - Im(Z0)
        pow_s[256] = d * d;
    }
    __syncthreads();

    // sparse mel projection + log
    if (tid < NMEL) {
        int m = tid;
        int lo = g_lo[m], hi = g_hi[m];
        float acc = 0.0f;
        const float* fr = fb + m * NFREQ;
        for (int f = lo; f <= hi; f++) acc = fmaf(fr[f], pow_s[f], acc);
        g_logmel[((size_t)(b * T + t)) * NMEL + m] = __logf(acc + LOG_GUARD);
    }
}

// ---------------------------------------------------------------------------
// stats: masked mean / unbiased std per (b, m), double accumulation
// ---------------------------------------------------------------------------
__global__ __launch_bounds__(256) void stats_kernel(
    const int* __restrict__ seq_len, int T)
{
    __shared__ double sh_s[256];
    __shared__ double sh_ss[256];
    int b = blockIdx.x;
    int m = threadIdx.x & 63;
    int ph = threadIdx.x >> 6;
    int flen = seq_len[b] / HOP + 1;

    double s = 0.0, ss = 0.0;
    for (int t = ph; t < flen; t += 4) {
        float v = g_logmel[((size_t)(b * T + t)) * NMEL + m];
        s += (double)v;
        ss += (double)v * (double)v;
    }
    sh_s[threadIdx.x] = s;
    sh_ss[threadIdx.x] = ss;
    __syncthreads();
    if (ph == 0) {
        #pragma unroll
        for (int i = 1; i < 4; i++) {
            s += sh_s[m + 64 * i];
            ss += sh_ss[m + 64 * i];
        }
        double n = (double)flen;
        double mean = s / n;
        double var = (ss - s * s / n) / (n - 1.0);
        if (var < 0.0) var = 0.0;
        double std = sqrt(var) + 1e-5;
        g_mean[b * NMEL + m] = (float)mean;
        g_rstd[b * NMEL + m] = (float)(1.0 / std);
    }
}

// ---------------------------------------------------------------------------
// normalize + transpose [b,t,m] -> [b,m,t], zero masked/pad frames,
// write feat_len tail (as float) if the output buffer carries it
// ---------------------------------------------------------------------------
__global__ __launch_bounds__(256) void out_kernel(
    const int* __restrict__ seq_len, float* __restrict__ out,
    int T, int TP, int extra)
{
    __shared__ float tile[64 * 65];
    __shared__ float mu[64];
    __shared__ float rs[64];

    int b = blockIdx.y;
    int t0 = blockIdx.x * 64;
    int flen = seq_len[b] / HOP + 1;

    if (threadIdx.x < 64) {
        mu[threadIdx.x] = g_mean[b * NMEL + threadIdx.x];
        rs[threadIdx.x] = g_rstd[b * NMEL + threadIdx.x];
    }
    __syncthreads();

    #pragma unroll
    for (int r = 0; r < 16; r++) {
        int idx = r * 256 + threadIdx.x;
        int m = idx & 63;
        int tl = idx >> 6;
        int t = t0 + tl;
        float v = 0.0f;
        if (t < flen) {
            v = (g_logmel[((size_t)(b * T + t)) * NMEL + m] - mu[m]) * rs[m];
        }
        tile[tl * 65 + m] = v;
    }
    __syncthreads();

    #pragma unroll
    for (int r = 0; r < 16; r++) {
        int idx = r * 256 + threadIdx.x;
        int tl = idx & 63;
        int m = idx >> 6;
        int t = t0 + tl;
        if (t < TP) out[((size_t)b * NMEL + m) * TP + t] = tile[tl * 65 + m];
    }

    if (blockIdx.x == 0 && threadIdx.x == 0 && b < extra) {
        // feat_len appended after the mel tensor, converted to output dtype
        size_t tail = (size_t)gridDim.y * NMEL * TP;
        out[tail + b] = (float)flen;
    }
}

// ---------------------------------------------------------------------------
extern "C" void kernel_launch(void* const* d_in, const int* in_sizes, int n_in,
                              void* d_out, int out_size)
{
    const float* x   = (const float*)d_in[0];
    const int*   seq = (const int*)d_in[1];
    const float* win = (const float*)d_in[2];
    const float* fb  = (const float*)d_in[3];
    float* out = (float*)d_out;

    int B = in_sizes[1];
    int L = in_sizes[0] / B;
    int T = L / HOP + 1;
    int TP = ((T + 15) / 16) * 16;

    init_kernel<<<1, 384>>>(fb);
    frame_kernel<<<dim3(T, B), 128>>>(x, win, fb, L, T);
    stats_kernel<<<B, 256>>>(seq, T);

    int nchunk = (TP + 63) / 64;
    long long extra = (long long)out_size - (long long)B * NMEL * TP;
    int ex = extra > 0 ? (int)(extra < B ? extra : B) : 0;
    out_kernel<<<dim3(nchunk, B), 256>>>(seq, out, T, TP, ex);
}

// round 2
// speedup vs baseline: 2.1809x; 2.1809x over previous
#include <cuda_runtime.h>

#define HOP 160
#define NFFT 512
#define NMEL 64
#define NFREQ 257
#define PREEMPH 0.97f
#define LOG_GUARD 5.9604644775390625e-8f   // 2^-24

#define MAXB 32
#define MAXT 1601
#define WPB 8    // warps (frames) per block

// ---- device scratch (no allocations allowed) ----
__device__ int    g_lo[NMEL], g_hi[NMEL];
__device__ float  g_mean[MAXB * NMEL];
__device__ float  g_rstd[MAXB * NMEL];
__device__ float  g_logmel[(size_t)MAXB * MAXT * NMEL];   // [b*T+t, m]

// ---------------------------------------------------------------------------
// init: mel filter support ranges (filters are triangular -> contiguous)
// ---------------------------------------------------------------------------
__global__ void init_kernel(const float* __restrict__ fb) {
    int m = threadIdx.x;
    if (m < NMEL) {
        int lo = NFREQ, hi = 0;
        const float* row = fb + m * NFREQ;
        for (int f = 0; f < NFREQ; f++) {
            if (row[f] != 0.0f) { if (f < lo) lo = f; hi = f; }
        }
        g_lo[m] = lo;
        g_hi[m] = hi;
    }
}

// ---------------------------------------------------------------------------
// frame kernel: ONE WARP per frame. 256-pt complex FFT fully in registers:
//   256 = 8 (regs, DFT8) x 32 (lanes, 5 shfl_xor radix-2 stages).
// No __syncthreads anywhere; shared used only for window + Z/pow staging.
// ---------------------------------------------------------------------------
__global__ __launch_bounds__(32 * WPB) void frame_kernel(
    const float* __restrict__ x, const float* __restrict__ win,
    const float* __restrict__ fb, int L, int T, int B)
{
    __shared__ float2 wsh[256];
    __shared__ float  sh_re[WPB][288];   // idx + (idx>>3) padding
    __shared__ float  sh_im[WPB][288];
    __shared__ float  sh_pow[WPB][264];

    const int tid = threadIdx.x;
    const float2* win2 = (const float2*)win;
    for (int i = tid; i < 256; i += 32 * WPB) wsh[i] = win2[i];
    __syncthreads();

    const int wid = tid >> 5;
    const int lane = tid & 31;
    const int fid = blockIdx.x * WPB + wid;
    if (fid >= B * T) return;
    const int b = fid / T;
    const int t = fid - b * T;
    const float* xb = x + (size_t)b * L;
    const int base = t * HOP - 256;

    // ---- pack: z[k] = y(2k) + i*y(2k+1), y = win * preemph(reflect(x)) ----
    float zr[8], zi[8];
    const bool fast = (t >= 2) && (t <= T - 3);   // uniform per warp
    #pragma unroll
    for (int p = 0; p < 8; p++) {
        int k = lane + 32 * p;
        float2 w2 = wsh[k];
        float vr = 0.0f, vi = 0.0f;
        if (w2.x != 0.0f || w2.y != 0.0f) {
            int n0 = base + 2 * k;
            if (fast) {
                float2 c = *(const float2*)(xb + n0);   // n0 even -> aligned
                float xm1 = xb[n0 - 1];
                vr = w2.x * (c.x - PREEMPH * xm1);
                vi = w2.y * (c.y - PREEMPH * c.x);
            } else {
                int q = n0 < 0 ? -n0 : n0;
                if (q >= L) q = 2 * (L - 1) - q;
                float y0 = (q == 0) ? xb[0] : (xb[q] - PREEMPH * xb[q - 1]);
                int n1 = n0 + 1;
                int q1 = n1 < 0 ? -n1 : n1;
                if (q1 >= L) q1 = 2 * (L - 1) - q1;
                float y1 = (q1 == 0) ? xb[0] : (xb[q1] - PREEMPH * xb[q1 - 1]);
                vr = w2.x * y0;
                vi = w2.y * y1;
            }
        }
        zr[p] = vr; zi[p] = vi;
    }

    // ---- per-lane DFT8 over p (DIF, constant twiddles) -> A[k1] ----
    {
        const float C = 0.70710678118654752f;
        float tr[4], ti[4], ur[4], ui[4];
        #pragma unroll
        for (int p = 0; p < 4; p++) {
            tr[p] = zr[p] + zr[p + 4];  ti[p] = zi[p] + zi[p + 4];
            ur[p] = zr[p] - zr[p + 4];  ui[p] = zi[p] - zi[p + 4];
        }
        // u1 *= (C,-C); u2 *= (0,-1); u3 *= (-C,-C)
        { float a = ur[1], bq = ui[1]; ur[1] = C * (a + bq); ui[1] = C * (bq - a); }
        { float a = ur[2], bq = ui[2]; ur[2] = bq; ui[2] = -a; }
        { float a = ur[3], bq = ui[3]; ur[3] = C * (bq - a); ui[3] = -C * (a + bq); }
        // DFT4 on t -> X0,X2,X4,X6 ; DFT4 on u -> X1,X3,X5,X7
        float ar = tr[0] + tr[2], ai = ti[0] + ti[2];
        float br = tr[0] - tr[2], bi = ti[0] - ti[2];
        float cr = tr[1] + tr[3], ci = ti[1] + ti[3];
        float dr = ti[1] - ti[3], di = -(tr[1] - tr[3]);   // (t1-t3)*(-i)
        zr[0] = ar + cr; zi[0] = ai + ci;
        zr[4] = ar - cr; zi[4] = ai - ci;
        zr[2] = br + dr; zi[2] = bi + di;
        zr[6] = br - dr; zi[6] = bi - di;
        ar = ur[0] + ur[2]; ai = ui[0] + ui[2];
        br = ur[0] - ur[2]; bi = ui[0] - ui[2];
        cr = ur[1] + ur[3]; ci = ui[1] + ui[3];
        dr = ui[1] - ui[3]; di = -(ur[1] - ur[3]);
        zr[1] = ar + cr; zi[1] = ai + ci;
        zr[5] = ar - cr; zi[5] = ai - ci;
        zr[3] = br + dr; zi[3] = bi + di;
        zr[7] = br - dr; zi[7] = bi - di;
    }

    // ---- per-lane twiddle: A[k1] *= exp(-2*pi*i*lane*k1/256) via chain ----
    {
        float s1, c1;
        sincospif((float)lane / 128.0f, &s1, &c1);   // w1 = (c1, -s1)
        float w1r = c1, w1i = -s1;
        float wr = 1.0f, wi = 0.0f;
        #pragma unroll
        for (int k1 = 0; k1 < 8; k1++) {
            if (k1) {
                float nr = zr[k1] * wr - zi[k1] * wi;
                zi[k1]   = zr[k1] * wi + zi[k1] * wr;
                zr[k1]   = nr;
            }
            float nwr = wr * w1r - wi * w1i;
            wi = wr * w1i + wi * w1r;
            wr = nwr;
        }
    }

    // ---- 32-pt cross-lane FFT (5 DIF radix-2 stages, shfl_xor) ----
    #pragma unroll
    for (int h = 16; h >= 1; h >>= 1) {
        int j = lane & (h - 1);
        float s, c;
        sincospif((float)j / (float)h, &s, &c);      // w = (c, -s)
        bool up = (lane & h) != 0;
        #pragma unroll
        for (int k1 = 0; k1 < 8; k1++) {
            float pr = __shfl_xor_sync(0xFFFFFFFFu, zr[k1], h);
            float pi = __shfl_xor_sync(0xFFFFFFFFu, zi[k1], h);
            if (up) {
                float dr = pr - zr[k1], di = pi - zi[k1];
                zr[k1] = dr * c + di * s;
                zi[k1] = di * c - dr * s;
            } else {
                zr[k1] += pr;
                zi[k1] += pi;
            }
        }
    }
    // lane holds X[k1 + 8*bitrev5(lane)]

    // ---- store Z to padded shared (conflict-free: 9*rev is odd-stride) ----
    {
        int rev = __brev(lane) >> 27;
        int a0 = 9 * rev;                  // (k1 + 8*rev) + ((k1+8*rev)>>3)
        #pragma unroll
        for (int k1 = 0; k1 < 8; k1++) {
            sh_re[wid][a0 + k1] = zr[k1];
            sh_im[wid][a0 + k1] = zi[k1];
        }
    }
    __syncwarp();

    // ---- real-FFT split + power spectrum ----
    {
        float bs, bc;
        sincospif((float)lane / 256.0f, &bs, &bc);
        float wr = bc, wi = -bs;                       // exp(-i*pi*f/256), f=lane
        const float STC = 0.92387953251128674f;        // cos(pi/8)
        const float STS = -0.38268343236508977f;       // -sin(pi/8)
        float powv[8];
        #pragma unroll
        for (int r = 0; r < 8; r++) {
            int f = lane + 32 * r;
            int g = (256 - f) & 255;
            float zfr = sh_re[wid][f + (f >> 3)], zfi = sh_im[wid][f + (f >> 3)];
            float zgr = sh_re[wid][g + (g >> 3)], zgi = sh_im[wid][g + (g >> 3)];
            float er = 0.5f * (zfr + zgr);
            float ei = 0.5f * (zfi - zgi);
            float orr = 0.5f * (zfi + zgi);
            float oi  = -0.5f * (zfr - zgr);
            float yr = er + wr * orr - wi * oi;
            float yi = ei + wr * oi + wi * orr;
            powv[r] = yr * yr + yi * yi;
            float nr = wr * STC - wi * STS;
            wi = wr * STS + wi * STC;
            wr = nr;
        }
        #pragma unroll
        for (int r = 0; r < 8; r++) sh_pow[wid][lane + 32 * r] = powv[r];
        if (lane == 0) {
            float d = sh_re[wid][0] - sh_im[wid][0];   // Y[256] = Re(Z0)-Im(Z0)
            sh_pow[wid][256] = d * d;
        }
    }
    __syncwarp();

    // ---- sparse mel projection + log ----
    #pragma unroll
    for (int mm = 0; mm < 2; mm++) {
        int m = lane + 32 * mm;
        int lo = g_lo[m], hi = g_hi[m];
        float acc = 0.0f;
        const float* frow = fb + m * NFREQ;
        for (int f = lo; f <= hi; f++)
            acc = fmaf(__ldg(frow + f), sh_pow[wid][f], acc);
        g_logmel[(size_t)fid * NMEL + m] = __logf(acc + LOG_GUARD);
    }
}

// ---------------------------------------------------------------------------
// stats: masked mean / unbiased std per (b, m); fp32 per-thread partials
// (<=101 items), double block reduction
// ---------------------------------------------------------------------------
__global__ __launch_bounds__(1024) void stats_kernel(
    const int* __restrict__ seq_len, int T)
{
    __shared__ double sh_s[1024];
    __shared__ double sh_ss[1024];
    int b = blockIdx.x;
    int m = threadIdx.x & 63;
    int ph = threadIdx.x >> 6;      // 16 phases
    int flen = seq_len[b] / HOP + 1;

    float s = 0.0f, ss = 0.0f;
    for (int t = ph; t < flen; t += 16) {
        float v = g_logmel[((size_t)(b * T + t)) * NMEL + m];
        s += v;
        ss = fmaf(v, v, ss);
    }
    sh_s[threadIdx.x] = (double)s;
    sh_ss[threadIdx.x] = (double)ss;
    __syncthreads();
    if (ph == 0) {
        double ds = 0.0, dss = 0.0;
        #pragma unroll
        for (int i = 0; i < 16; i++) {
            ds += sh_s[m + 64 * i];
            dss += sh_ss[m + 64 * i];
        }
        double n = (double)flen;
        double mean = ds / n;
        double var = (dss - ds * ds / n) / (n - 1.0);
        if (var < 0.0) var = 0.0;
        double std = sqrt(var) + 1e-5;
        g_mean[b * NMEL + m] = (float)mean;
        g_rstd[b * NMEL + m] = (float)(1.0 / std);
    }
}

// ---------------------------------------------------------------------------
// normalize + transpose [b,t,m] -> [b,m,t], zero masked/pad frames,
// optional feat_len tail
// ---------------------------------------------------------------------------
__global__ __launch_bounds__(256) void out_kernel(
    const int* __restrict__ seq_len, float* __restrict__ out,
    int T, int TP, int extra)
{
    __shared__ float tile[64 * 65];
    __shared__ float mu[64];
    __shared__ float rs[64];

    int b = blockIdx.y;
    int t0 = blockIdx.x * 64;
    int flen = seq_len[b] / HOP + 1;

    if (threadIdx.x < 64) {
        mu[threadIdx.x] = g_mean[b * NMEL + threadIdx.x];
        rs[threadIdx.x] = g_rstd[b * NMEL + threadIdx.x];
    }
    __syncthreads();

    #pragma unroll
    for (int r = 0; r < 16; r++) {
        int idx = r * 256 + threadIdx.x;
        int m = idx & 63;
        int tl = idx >> 6;
        int t = t0 + tl;
        float v = 0.0f;
        if (t < flen) {
            v = (g_logmel[((size_t)(b * T + t)) * NMEL + m] - mu[m]) * rs[m];
        }
        tile[tl * 65 + m] = v;
    }
    __syncthreads();

    #pragma unroll
    for (int r = 0; r < 16; r++) {
        int idx = r * 256 + threadIdx.x;
        int tl = idx & 63;
        int m = idx >> 6;
        int t = t0 + tl;
        if (t < TP) out[((size_t)b * NMEL + m) * TP + t] = tile[tl * 65 + m];
    }

    if (blockIdx.x == 0 && threadIdx.x == 0 && b < extra) {
        size_t tail = (size_t)gridDim.y * NMEL * TP;
        out[tail + b] = (float)flen;
    }
}

// ---------------------------------------------------------------------------
extern "C" void kernel_launch(void* const* d_in, const int* in_sizes, int n_in,
                              void* d_out, int out_size)
{
    const float* x   = (const float*)d_in[0];
    const int*   seq = (const int*)d_in[1];
    const float* win = (const float*)d_in[2];
    const float* fb  = (const float*)d_in[3];
    float* out = (float*)d_out;

    int B = in_sizes[1];
    int L = in_sizes[0] / B;
    int T = L / HOP + 1;
    int TP = ((T + 15) / 16) * 16;

    init_kernel<<<1, 64>>>(fb);

    int nframes = B * T;
    int nblocks = (nframes + WPB - 1) / WPB;
    frame_kernel<<<nblocks, 32 * WPB>>>(x, win, fb, L, T, B);

    stats_kernel<<<B, 1024>>>(seq, T);

    int nchunk = (TP + 63) / 64;
    long long extra = (long long)out_size - (long long)B * NMEL * TP;
    int ex = extra > 0 ? (int)(extra < B ? extra : B) : 0;
    out_kernel<<<dim3(nchunk, B), 256>>>(seq, out, T, TP, ex);
}